// round 4
// baseline (speedup 1.0000x reference)
#include <cuda_runtime.h>
#include <cuda_bf16.h>
#include <math.h>

#define Hdim 256
#define Wdim 256
#define HW   65536
#define CC   12
#define BB   8
#define BC   96
#define SENT 600        // u16 sentinel: 600^2 = 360000 > max real d^2 (130050)

// Scratch (device globals; no allocation allowed)
__device__ unsigned int g_v [BC * HW];   // packed vertical dists: P | (N<<16)
__device__ float g_dt  [BC * HW];        // signed distance dt = neg - pos
__device__ int   g_hasfg[BC];
__device__ float g_minmax[BC * 2];       // (min, max) per bc  -- atomic
__device__ float g_dsum  [BC * 2];       // (sum d, sum d^2)    -- atomic (k_hmin)
__device__ float g_sums  [BC * 3];       // (sum p*d, sum p, sum p^2) (k_sums)

__device__ __forceinline__ float atomicMinFloat(float* a, float v) {
    return (v >= 0.0f)
        ? __int_as_float(atomicMin((int*)a, __float_as_int(v)))
        : __uint_as_float(atomicMax((unsigned*)a, __float_as_uint(v)));
}
__device__ __forceinline__ float atomicMaxFloat(float* a, float v) {
    return (v >= 0.0f)
        ? __int_as_float(atomicMax((int*)a, __float_as_int(v)))
        : __uint_as_float(atomicMin((unsigned*)a, __float_as_uint(v)));
}

// ---------------------------------------------------------------------------
// K0: reset atomic accumulators (device globals persist across graph replays)
// ---------------------------------------------------------------------------
__global__ void k_init() {
    const int i = threadIdx.x;
    if (i < BC) {
        g_minmax[i * 2]     =  1e30f;
        g_minmax[i * 2 + 1] = -1e30f;
        g_hasfg[i] = 0;
    }
    if (i < BC * 3) g_sums[i] = 0.0f;
    if (i < BC * 2) g_dsum[i] = 0.0f;
}

// ---------------------------------------------------------------------------
// K1: vertical 1D distance-to-zero per column, packed u16 pair (P | N<<16).
// Grid BC*2, block 128: each block owns 128 columns of one (b,c).
// Pass 1 down-scan stages up-dists; pass 2 up-scan combines (staged P==0
// <=> bg pixel, so no second targets read).
// ---------------------------------------------------------------------------
__global__ void __launch_bounds__(128) k_vert(const int* __restrict__ targets) {
    const int bc = blockIdx.x >> 1;
    const int b  = bc / CC, c = bc % CC;
    const int w  = ((blockIdx.x & 1) << 7) + threadIdx.x;
    const int* tb = targets + b * HW;
    unsigned int* V = g_v + bc * HW;

    int upP = -100000;   // last bg row (zero of m)
    int upN = -100000;   // last fg row (zero of ~m)
    int anyfg = 0;
    #pragma unroll 8
    for (int h = 0; h < Hdim; ++h) {
        const int fg = (tb[h * Wdim + w] == c);
        anyfg |= fg;
        if (!fg) upP = h;
        if ( fg) upN = h;
        const unsigned pP = (unsigned)min(h - upP, SENT);
        const unsigned pN = (unsigned)min(h - upN, SENT);
        V[h * Wdim + w] = pP | (pN << 16);
    }
    int dnP = 100000, dnN = 100000;
    #pragma unroll 8
    for (int h = Hdim - 1; h >= 0; --h) {
        const unsigned v = V[h * Wdim + w];
        const int aP = (int)(v & 0xffffu);
        const int aN = (int)(v >> 16);
        const int fg = (aP != 0);       // staged up-dist 0 <=> bg pixel
        if (!fg) dnP = h;
        if ( fg) dnN = h;
        const unsigned rP = (unsigned)min(min(aP, dnP - h), SENT);
        const unsigned rN = (unsigned)min(min(aN, dnN - h), SENT);
        V[h * Wdim + w] = rP | (rN << 16);
    }
    if (__syncthreads_or(anyfg)) {
        if (threadIdx.x == 0) atomicOr(&g_hasfg[bc], 1);
    }
}

// ---------------------------------------------------------------------------
// K2: horizontal exact min-plus via outward search with early exit.
//   d2(j) = min_k (j-k)^2 + g2[k];  scan outward from k=j, stop when
//   r^2 >= best (exact). Each pixel needs only ONE transform
//   (fg pixel -> P, bg pixel -> N). 4 rows per block (1024 threads).
//   Fused block reduction: per-(b,c) min, max, sum(dt), sum(dt^2).
// ---------------------------------------------------------------------------
__global__ void __launch_bounds__(1024) k_hmin() {
    const int t  = threadIdx.x;
    const int r4 = t >> 8;                 // local row 0..3
    const int j  = t & 255;
    const int rowg = (blockIdx.x << 2) + r4;   // global row in [0, BC*H)
    const int bc   = rowg >> 8;

    __shared__ float shP[4][768];          // [256..512) real, pads = +INF
    __shared__ float shN[4][768];
    const unsigned v = g_v[rowg * Wdim + j];
    const int vPi = (int)(v & 0xffffu);
    const int vNi = (int)(v >> 16);
    const float fP = (float)vPi, fN = (float)vNi;
    shP[r4][j]       = 1.0e9f;  shN[r4][j]       = 1.0e9f;
    shP[r4][256 + j] = fP * fP; shN[r4][256 + j] = fN * fN;
    shP[r4][512 + j] = 1.0e9f;  shN[r4][512 + j] = 1.0e9f;
    const bool fg = (vPi != 0);
    const int  hf = g_hasfg[bc];
    __syncthreads();

    const float* s = (fg ? shP[r4] : shN[r4]) + 256 + j;
    float best = s[0];
    float rr = 1.0f, rr1 = 4.0f, f4 = 4.0f;   // r^2, (r+1)^2, 4r at r=1
    #pragma unroll 1
    for (int r = 1; r < 256; r += 2) {
        if (rr >= best) break;
        const float a = fminf(rr  + s[-r],       rr  + s[r]);
        const float b = fminf(rr1 + s[-(r + 1)], rr1 + s[r + 1]);
        best = fminf(best, fminf(a, b));
        rr  += f4 + 4.0f;
        rr1 += f4 + 8.0f;
        f4  += 8.0f;
    }
    float dt = fg ? -sqrtf(best) : sqrtf(best);
    if (!hf) dt = 0.0f;
    g_dt[rowg * Wdim + j] = dt;

    // fused block reduction: min, max, sum, sum of squares
    float mn = dt, mx = dt, sd = dt, sd2 = dt * dt;
    #pragma unroll
    for (int o = 16; o; o >>= 1) {
        mn  = fminf(mn, __shfl_xor_sync(0xffffffffu, mn, o));
        mx  = fmaxf(mx, __shfl_xor_sync(0xffffffffu, mx, o));
        sd  += __shfl_xor_sync(0xffffffffu, sd,  o);
        sd2 += __shfl_xor_sync(0xffffffffu, sd2, o);
    }
    __shared__ float red[4][32];
    const int wid = t >> 5, lane = t & 31;
    if (lane == 0) { red[0][wid] = mn; red[1][wid] = mx; red[2][wid] = sd; red[3][wid] = sd2; }
    __syncthreads();
    if (t < 32) {
        mn = red[0][t]; mx = red[1][t]; sd = red[2][t]; sd2 = red[3][t];
        #pragma unroll
        for (int o = 16; o; o >>= 1) {
            mn  = fminf(mn, __shfl_xor_sync(0xffffffffu, mn, o));
            mx  = fmaxf(mx, __shfl_xor_sync(0xffffffffu, mx, o));
            sd  += __shfl_xor_sync(0xffffffffu, sd,  o);
            sd2 += __shfl_xor_sync(0xffffffffu, sd2, o);
        }
        if (t == 0) {
            atomicMinFloat(&g_minmax[bc * 2],     mn);
            atomicMaxFloat(&g_minmax[bc * 2 + 1], mx);
            atomicAdd(&g_dsum[bc * 2],     sd);
            atomicAdd(&g_dsum[bc * 2 + 1], sd2);
        }
    }
}

// ---------------------------------------------------------------------------
// K3: fused softmax + raw dice moments. Accumulates per class:
//   Spd = sum p*dt,  Sp = sum p,  Sp2 = sum p^2   (no normalization here).
// Grid: (b, 32 row-groups) = 256 blocks; thread handles one column x 8 rows.
// ---------------------------------------------------------------------------
__global__ void __launch_bounds__(256, 3) k_sums(const float* __restrict__ logits) {
    const int blk = blockIdx.x;            // b*32 + rowgroup
    const int b   = blk >> 5;
    const int h0  = (blk & 31) * 8;
    const int w   = threadIdx.x;

    float aI[CC], aS[CC], aP2[CC];
    #pragma unroll
    for (int c = 0; c < CC; ++c) { aI[c] = 0.0f; aS[c] = 0.0f; aP2[c] = 0.0f; }

    const int boffL = b * CC * HW;
    for (int r = 0; r < 8; ++r) {
        const int pix = (h0 + r) * Wdim + w;
        float l[CC];
        float mxl = -1e30f;
        #pragma unroll
        for (int c = 0; c < CC; ++c) {
            l[c] = logits[boffL + c * HW + pix];
            mxl = fmaxf(mxl, l[c]);
        }
        float s = 0.0f;
        #pragma unroll
        for (int c = 0; c < CC; ++c) { l[c] = __expf(l[c] - mxl); s += l[c]; }
        const float rs = 1.0f / s;
        #pragma unroll
        for (int c = 0; c < CC; ++c) {
            const float p = l[c] * rs;
            const float d = g_dt[boffL + c * HW + pix];
            aI [c] = fmaf(p, d, aI [c]);
            aS [c] += p;
            aP2[c] = fmaf(p, p, aP2[c]);
        }
    }

    #pragma unroll
    for (int c = 0; c < CC; ++c) {
        #pragma unroll
        for (int o = 16; o; o >>= 1) {
            aI [c] += __shfl_xor_sync(0xffffffffu, aI [c], o);
            aS [c] += __shfl_xor_sync(0xffffffffu, aS [c], o);
            aP2[c] += __shfl_xor_sync(0xffffffffu, aP2[c], o);
        }
    }
    __shared__ float sred[36][8];
    const int lane = w & 31, wi = w >> 5;
    if (lane == 0) {
        #pragma unroll
        for (int c = 0; c < CC; ++c) {
            sred[c * 3 + 0][wi] = aI [c];
            sred[c * 3 + 1][wi] = aS [c];
            sred[c * 3 + 2][wi] = aP2[c];
        }
    }
    __syncthreads();
    if (w < 36) {
        float acc = 0.0f;
        #pragma unroll
        for (int i = 0; i < 8; ++i) acc += sred[w][i];
        const int c    = w / 3;
        const int comp = w - c * 3;
        atomicAdd(&g_sums[(b * CC + c) * 3 + comp], acc);
    }
}

// ---------------------------------------------------------------------------
// K4: final dice mean over 96 (b,c) pairs, reconstructing normalized sums:
//   inter = inv*(Spd - dmin*Sp)
//   D2    = inv^2*(Sd2 - 2*dmin*Sd + N*dmin^2)
// ---------------------------------------------------------------------------
__global__ void k_final(float* __restrict__ out) {
    __shared__ float s[128];
    const int i = threadIdx.x;
    float li = 0.0f;
    if (i < BC) {
        const float dmin = g_minmax[i * 2];
        const float dmax = g_minmax[i * 2 + 1];
        const float inv  = 1.0f / (dmax - dmin + 1e-8f);
        const float Spd  = g_sums[i * 3];
        const float Sp   = g_sums[i * 3 + 1];
        const float Sp2  = g_sums[i * 3 + 2];
        const float Sd   = g_dsum[i * 2];
        const float Sd2  = g_dsum[i * 2 + 1];
        const float I  = inv * (Spd - dmin * Sp);
        const float D2 = inv * inv * (Sd2 - 2.0f * dmin * Sd + 65536.0f * dmin * dmin);
        li = 1.0f - 2.0f * I / (Sp2 + D2 + 1e-6f);
    }
    s[i] = li;
    __syncthreads();
    #pragma unroll
    for (int o = 64; o; o >>= 1) {
        if (i < o) s[i] += s[i + o];
        __syncthreads();
    }
    if (i == 0) out[0] = s[0] / (float)BC;
}

extern "C" void kernel_launch(void* const* d_in, const int* in_sizes, int n_in,
                              void* d_out, int out_size) {
    const float* logits  = (const float*)d_in[0];
    const int*   targets = (const int*)d_in[1];
    float* out = (float*)d_out;

    k_init <<<1, 512>>>();
    k_vert <<<BC * 2, 128>>>(targets);
    k_hmin <<<BC * 64, 1024>>>();
    k_sums <<<BB * 32, 256>>>(logits);
    k_final<<<1, 128>>>(out);
}